// round 15
// baseline (speedup 1.0000x reference)
#include <cuda_runtime.h>
#include <cuda_fp16.h>
#include <cstdint>
#include <cstddef>

#define BB    2
#define SS    4096
#define HIDD  2048
#define HH    16
#define KVH   4
#define HDD   128
#define KP    1024
#define NBH   (BB * HH)
#define QK_SCALE 0.08838834764831843f

// ---------------- scratch ----------------
__device__ float g_qkv [(size_t)BB * SS * 3072];
__device__ float g_pk  [(size_t)8 * KP * HDD];
__device__ float g_pv  [(size_t)8 * KP * HDD];
__device__ __half g_Ahi [(size_t)BB * SS * 2048];   // hs planes, then attn planes
__device__ __half g_Alo [(size_t)BB * SS * 2048];
__device__ __half g_Wthi[(size_t)3072 * 2048];
__device__ __half g_qhi [(size_t)BB * SS * 2048];
__device__ __half g_qlo [(size_t)BB * SS * 2048];
__device__ __half g_ETFhi[(size_t)2048 * 4096];
__device__ __half g_ETFlo[(size_t)2048 * 4096];
__device__ __half g_kvThi[(size_t)16 * 128 * 4096]; // hi only (B of pkpv)
__device__ __half g_pkhi[(size_t)8 * KP * HDD];
__device__ __half g_pklo[(size_t)8 * KP * HDD];     // kept: scores stays 3-product
__device__ __half g_pvThi[(size_t)8 * HDD * KP];    // hi only (B of P@V)
__device__ float g_bias[3072];

// ---------------- PTX helpers ----------------
__device__ __forceinline__ uint32_t smem_u32(const void* p) {
    uint32_t a;
    asm("{ .reg .u64 t; cvta.to.shared.u64 t, %1; cvt.u32.u64 %0, t; }" : "=r"(a) : "l"(p));
    return a;
}
__device__ __forceinline__ void ldsm_x4(uint32_t* r, uint32_t addr) {
    asm volatile("ldmatrix.sync.aligned.m8n8.x4.shared.b16 {%0,%1,%2,%3}, [%4];"
                 : "=r"(r[0]), "=r"(r[1]), "=r"(r[2]), "=r"(r[3]) : "r"(addr));
}
__device__ __forceinline__ void mma16816(float* c, const uint32_t* a, uint32_t b0, uint32_t b1) {
    asm volatile("mma.sync.aligned.m16n8k16.row.col.f32.f16.f16.f32 "
                 "{%0,%1,%2,%3}, {%4,%5,%6,%7}, {%8,%9}, {%0,%1,%2,%3};"
                 : "+f"(c[0]), "+f"(c[1]), "+f"(c[2]), "+f"(c[3])
                 : "r"(a[0]), "r"(a[1]), "r"(a[2]), "r"(a[3]), "r"(b0), "r"(b1));
}
__device__ __forceinline__ void cp_async16(uint32_t dst, const void* src) {
    asm volatile("cp.async.cg.shared.global [%0], [%1], 16;" :: "r"(dst), "l"(src));
}
#define CP_COMMIT()  asm volatile("cp.async.commit_group;" ::: "memory")
#define CP_WAIT(n)   asm volatile("cp.async.wait_group %0;" :: "n"(n) : "memory")

__device__ __forceinline__ __half h_hi(float v) { return __float2half_rn(v); }
__device__ __forceinline__ __half h_lo(float v, __half h) {
    return __float2half_rn(v - __half2float(h));
}
__device__ __forceinline__ uint32_t pack_h2(__half a, __half b) {
    __half2 t(a, b);
    return *reinterpret_cast<uint32_t*>(&t);
}

// ---------------- splits / transposes ----------------
__global__ __launch_bounds__(256) void split_h(
    const float4* __restrict__ x, uint2* __restrict__ hi, uint2* __restrict__ lo, int n4)
{
    int i = blockIdx.x * 256 + threadIdx.x;
    if (i >= n4) return;
    float4 v = x[i];
    __half h0 = h_hi(v.x), h1 = h_hi(v.y), h2 = h_hi(v.z), h3 = h_hi(v.w);
    uint2 uh; uh.x = pack_h2(h0, h1); uh.y = pack_h2(h2, h3);
    uint2 ul; ul.x = pack_h2(h_lo(v.x, h0), h_lo(v.y, h1));
    ul.y = pack_h2(h_lo(v.z, h2), h_lo(v.w, h3));
    hi[i] = uh; lo[i] = ul;
}

// Tlo may be nullptr (lo plane unused -> skip the store)
__global__ __launch_bounds__(256) void transpose_split(
    const float* __restrict__ W, __half* __restrict__ Thi,
    __half* __restrict__ Tlo, int Nsrc, int rowOff, int ldT)
{
    __shared__ float t[32][33];
    const int n0 = blockIdx.x * 32, k0 = blockIdx.y * 32;
    const int tx = threadIdx.x & 31, ty = threadIdx.x >> 5;
#pragma unroll
    for (int j = 0; j < 32; j += 8)
        t[ty + j][tx] = W[(long)(k0 + ty + j) * Nsrc + n0 + tx];
    __syncthreads();
#pragma unroll
    for (int j = 0; j < 32; j += 8) {
        float v = t[tx][ty + j];
        long o = (long)(rowOff + n0 + ty + j) * ldT + k0 + tx;
        __half h = h_hi(v);
        Thi[o] = h;
        if (Tlo) Tlo[o] = h_lo(v, h);
    }
}

// k/v slices -> transposed hi plane only [z][128 d][4096 s]
__global__ __launch_bounds__(256) void kv_tsplit()
{
    __shared__ float t[32][33];
    const int z = blockIdx.z, sel = z >> 3, b = (z >> 2) & 1, kv = z & 3;
    const int s0 = blockIdx.x * 32, d0 = blockIdx.y * 32;
    const int tx = threadIdx.x & 31, ty = threadIdx.x >> 5;
    const float* src = g_qkv + (size_t)b * SS * 3072 + 2048 + sel * 512 + kv * 128;
#pragma unroll
    for (int j = 0; j < 32; j += 8)
        t[ty + j][tx] = src[(long)(s0 + ty + j) * 3072 + d0 + tx];
    __syncthreads();
    __half* dh = g_kvThi + (size_t)z * 128 * 4096;
#pragma unroll
    for (int j = 0; j < 32; j += 8)
        dh[(long)(d0 + ty + j) * 4096 + s0 + tx] = h_hi(t[tx][ty + j]);
}

// g_pv -> pvT hi plane only [sl][128 d][1024 key]
__global__ __launch_bounds__(256) void pv_tsplit()
{
    __shared__ float t[32][33];
    const int z = blockIdx.z;
    const int k0 = blockIdx.x * 32, d0 = blockIdx.y * 32;
    const int tx = threadIdx.x & 31, ty = threadIdx.x >> 5;
    const float* src = g_pv + (size_t)z * KP * HDD;
#pragma unroll
    for (int j = 0; j < 32; j += 8)
        t[ty + j][tx] = src[(long)(k0 + ty + j) * 128 + d0 + tx];
    __syncthreads();
    __half* dh = g_pvThi + (size_t)z * HDD * KP;
#pragma unroll
    for (int j = 0; j < 32; j += 8)
        dh[(long)(d0 + ty + j) * 1024 + k0 + tx] = h_hi(t[tx][ty + j]);
}

__global__ void combine_bias(const float* __restrict__ bq, const float* __restrict__ bk,
                             const float* __restrict__ bv, float* __restrict__ out)
{
    int i = blockIdx.x * 256 + threadIdx.x;
    if (i < 2048) out[i] = bq[i];
    else if (i < 2560) out[i] = bk[i - 2048];
    else if (i < 3072) out[i] = bv[i - 2560];
}

// ---------------- fp16 2-product GEMM, BK=64, 2 stages, 2 CTAs/SM, persistent ----------------
// smem tile: 128 rows x 128B data, 144B stride (ldsm conflict-free)
#define TILE_B  18432            // 128 * 144
#define STAGE_B (3 * TILE_B)     // Ah, Al, Bh = 55296
#define NSTAGE  2
#define GEMM_SMEM (NSTAGE * STAGE_B)   // 110592 -> 2 CTAs/SM
#define PERSIST_GRID 296               // 148 SMs x 2 CTAs

__device__ __forceinline__ void mma_body(
    const __half* __restrict__ Ahi, const __half* __restrict__ Alo, long lda,
    const __half* __restrict__ Bhi, long ldb,
    const float* __restrict__ bias, float* __restrict__ C, long ldc,
    int K, long m0, long n0, char* smem)
{
    const uint32_t sbase = smem_u32(smem);
    const int tid  = threadIdx.x;
    const int lane = tid & 31;
    const int wid  = tid >> 5;
    const int wm   = wid >> 2;
    const int wn   = wid & 3;

    const __half* gsrc[3] = { Ahi, Alo, Bhi };

    // one stage = 3 tiles of 128 rows x 64 halves (128B); 12 cp.async/thread
    auto prefetch = [&](int kt, int st) {
#pragma unroll
        for (int i = 0; i < 12; i++) {
            const int t   = i >> 2;                 // tile 0..2
            const int idx = tid + (i & 3) * 256;    // 0..1023 within tile
            const int r   = idx >> 3;
            const int sg  = idx & 7;
            const long row = (t < 2 ? m0 : n0) + r;
            const long ld  = (t < 2 ? lda : ldb);
            cp_async16(sbase + st * STAGE_B + t * TILE_B + r * 144 + sg * 16,
                       gsrc[t] + row * ld + kt + sg * 8);
        }
        CP_COMMIT();
    };

    float acc[4][4][4];
#pragma unroll
    for (int i = 0; i < 4; i++)
#pragma unroll
        for (int j = 0; j < 4; j++)
#pragma unroll
            for (int k = 0; k < 4; k++) acc[i][j][k] = 0.0f;

    const int nch = K >> 6;
    prefetch(0, 0);

    const int q  = lane >> 3;
    const int rq = lane & 7;

    for (int ch = 0; ch < nch; ch++) {
        if (ch + 1 < nch) { prefetch((ch + 1) << 6, (ch + 1) & 1); CP_WAIT(1); }
        else              { CP_WAIT(0); }
        __syncthreads();

        const uint32_t sb = sbase + (ch & 1) * STAGE_B;
        const uint32_t AH = sb, AL = sb + TILE_B, BH = sb + 2 * TILE_B;

#pragma unroll
        for (int kc = 0; kc < 4; kc++) {
            const int koff = kc * 32;
            uint32_t ah[4][4], al[4][4], bh[2][4];
#pragma unroll
            for (int mf = 0; mf < 4; mf++) {
                uint32_t off = (uint32_t)((wm * 64 + mf * 16 + (q & 1) * 8 + rq) * 144
                                          + koff + (q >> 1) * 16);
                ldsm_x4(ah[mf], AH + off);
                ldsm_x4(al[mf], AL + off);
            }
#pragma unroll
            for (int pr = 0; pr < 2; pr++) {
                uint32_t off = (uint32_t)((wn * 32 + pr * 16 + (q >> 1) * 8 + rq) * 144
                                          + koff + (q & 1) * 16);
                ldsm_x4(bh[pr], BH + off);
            }
#pragma unroll
            for (int mf = 0; mf < 4; mf++)
#pragma unroll
                for (int nf = 0; nf < 4; nf++) {
                    const int pr = nf >> 1, w2 = (nf & 1) * 2;
                    mma16816(acc[mf][nf], ah[mf], bh[pr][w2], bh[pr][w2 + 1]);
                    mma16816(acc[mf][nf], al[mf], bh[pr][w2], bh[pr][w2 + 1]);
                }
        }
        __syncthreads();   // protect stage (ch&1) from iteration ch+1's prefetch of ch+2
    }

    const int g   = lane >> 2;
    const int tig = lane & 3;
#pragma unroll
    for (int mf = 0; mf < 4; mf++) {
        const long mrow = m0 + wm * 64 + mf * 16 + g;
#pragma unroll
        for (int nf = 0; nf < 4; nf++) {
            const long col = n0 + wn * 32 + nf * 8 + tig * 2;
            float b0 = 0.f, b1 = 0.f;
            if (bias) { b0 = bias[col]; b1 = bias[col + 1]; }
            float2 v0 = { acc[mf][nf][0] + b0, acc[mf][nf][1] + b1 };
            float2 v1 = { acc[mf][nf][2] + b0, acc[mf][nf][3] + b1 };
            *(float2*)&C[mrow * ldc + col]       = v0;
            *(float2*)&C[(mrow + 8) * ldc + col] = v1;
        }
    }
}

// persistent: each CTA loops over tile indices (n-fastest order, as before)
__global__ __launch_bounds__(256, 2) void gemm_mma(
    const __half* __restrict__ Ahi, const __half* __restrict__ Alo,
    const __half* __restrict__ Bhi,
    const float* __restrict__ bias, float* __restrict__ C, int K, int ldc,
    int ntn, int ntiles)
{
    extern __shared__ char smem[];
    for (int t = blockIdx.x; t < ntiles; t += gridDim.x) {
        long m0 = (long)(t / ntn) * 128;
        long n0 = (long)(t % ntn) * 128;
        mma_body(Ahi, Alo, K, Bhi, K, bias, C, ldc, K, m0, n0, smem);
        __syncthreads();   // all smem reads of this tile done before next tile's prefetch
    }
}

__global__ __launch_bounds__(256, 2) void pkpv_mma()
{
    extern __shared__ char smem[];
    const int z = blockIdx.z, sel = z >> 3, sl = z & 7;
    const __half* Ah = g_ETFhi + (size_t)sel * 1024 * 4096;
    const __half* Al = g_ETFlo + (size_t)sel * 1024 * 4096;
    const __half* Bh = g_kvThi + (size_t)z * 128 * 4096;
    float* C = (sel ? g_pv : g_pk) + (size_t)sl * KP * HDD;
    mma_body(Ah, Al, 4096, Bh, 4096, nullptr, C, 128, 4096,
             (long)blockIdx.y * 128, 0, smem);
}

// ---------------- fused flash attention (fp16, BQ=64, single-buffer, 2 CTAs/SM) ----------------
#define FQ_QH  0u
#define FQ_QL  17408u
#define FQ_PKH 34816u       // 64 x 272
#define FQ_PKL 52224u
#define FQ_PV  69632u       // 128 x 144
#define FQ_PH  88064u       // 64 x 144
#define FQ_PL  97280u
#define FQ_RED 106496u      // 64 rows x 4 floats
#define FL_SMEM 107520      // x2 CTAs = 215040 <= 228KB

__global__ __launch_bounds__(256, 2) void flash_attn()
{
    extern __shared__ char smem[];
    const uint32_t sbase = smem_u32(smem);
    float* red = (float*)(smem + FQ_RED);

    const int tid  = threadIdx.x;
    const int lane = tid & 31;
    const int w    = tid >> 5;
    const int wm   = w >> 2;
    const int wn   = w & 3;
    const int q4   = lane >> 3;
    const int rq   = lane & 7;
    const int g    = lane >> 2;
    const int tig  = lane & 3;

    const int bh = blockIdx.y, b = bh >> 4, h = bh & 15;
    const int sl = b * KVH + (h >> 2);
    const long qrow0 = (long)b * SS + blockIdx.x * 64;
    const size_t pkOff = (size_t)sl * KP * HDD;
    const size_t pvOff = (size_t)sl * HDD * KP;

    auto pf_chunk = [&](int c) {
#pragma unroll
        for (int i = 0; i < 8; i++) {              // pk hi+lo: 64 x 256B x2
            int idx = tid + i * 256;
            int plane = idx >> 10, rem = idx & 1023;
            int r = rem >> 4, sg = rem & 15;
            const __half* src = (plane ? g_pklo : g_pkhi) + pkOff + (size_t)(c * 64 + r) * 128 + sg * 8;
            cp_async16(sbase + (plane ? FQ_PKL : FQ_PKH) + r * 272 + sg * 16, src);
        }
#pragma unroll
        for (int i = 0; i < 4; i++) {              // pvT hi: 128 x 128B
            int idx = tid + i * 256;
            int r = idx >> 3, sg = idx & 7;
            const __half* src = g_pvThi + pvOff + (size_t)r * KP + c * 64 + sg * 8;
            cp_async16(sbase + FQ_PV + r * 144 + sg * 16, src);
        }
        CP_COMMIT();
    };

    {   // q planes + chunk 0, one group
#pragma unroll
        for (int i = 0; i < 8; i++) {
            int idx = tid + i * 256;
            int plane = idx >> 10, rem = idx & 1023;
            int r = rem >> 4, sg = rem & 15;
            const __half* src = (plane ? g_qlo : g_qhi) + (qrow0 + r) * 2048 + h * 128 + sg * 8;
            cp_async16(sbase + (plane ? FQ_QL : FQ_QH) + r * 272 + sg * 16, src);
        }
        pf_chunk(0);
    }

    float oacc[2][4][4];
#pragma unroll
    for (int i = 0; i < 2; i++)
#pragma unroll
        for (int j = 0; j < 4; j++)
#pragma unroll
            for (int k = 0; k < 4; k++) oacc[i][j][k] = 0.0f;
    float mrun[2][2] = {{-1e30f, -1e30f}, {-1e30f, -1e30f}};
    float lrun[2][2] = {{0.f, 0.f}, {0.f, 0.f}};

    for (int c = 0; c < 16; c++) {
        CP_WAIT(0);
        __syncthreads();

        // ---- S = q @ pk^T (64x64), fp16 x3 ----
        float accs[2][2][4];
#pragma unroll
        for (int i = 0; i < 2; i++)
#pragma unroll
            for (int j = 0; j < 2; j++)
#pragma unroll
                for (int k = 0; k < 4; k++) accs[i][j][k] = 0.0f;
#pragma unroll
        for (int ks = 0; ks < 8; ks++) {
            uint32_t qh[2][4], ql[2][4], kb[4], kl[4];
#pragma unroll
            for (int mf = 0; mf < 2; mf++) {
                uint32_t off = (uint32_t)((wm * 32 + mf * 16 + (q4 & 1) * 8 + rq) * 272
                                          + ks * 32 + (q4 >> 1) * 16);
                ldsm_x4(qh[mf], sbase + FQ_QH + off);
                ldsm_x4(ql[mf], sbase + FQ_QL + off);
            }
            {
                uint32_t off = (uint32_t)((wn * 16 + (q4 >> 1) * 8 + rq) * 272
                                          + ks * 32 + (q4 & 1) * 16);
                ldsm_x4(kb, sbase + FQ_PKH + off);
                ldsm_x4(kl, sbase + FQ_PKL + off);
            }
#pragma unroll
            for (int mf = 0; mf < 2; mf++)
#pragma unroll
                for (int nf = 0; nf < 2; nf++) {
                    const int w2 = nf * 2;
                    mma16816(accs[mf][nf], qh[mf], kb[w2], kb[w2 + 1]);
                    mma16816(accs[mf][nf], ql[mf], kb[w2], kb[w2 + 1]);
                    mma16816(accs[mf][nf], qh[mf], kl[w2], kl[w2 + 1]);
                }
        }

        // ---- online softmax ----
#pragma unroll
        for (int mf = 0; mf < 2; mf++)
#pragma unroll
            for (int hf = 0; hf < 2; hf++) {
                float cm = fmaxf(fmaxf(accs[mf][0][hf * 2], accs[mf][0][hf * 2 + 1]),
                                 fmaxf(accs[mf][1][hf * 2], accs[mf][1][hf * 2 + 1]));
                cm = fmaxf(cm, __shfl_xor_sync(0xffffffffu, cm, 1));
                cm = fmaxf(cm, __shfl_xor_sync(0xffffffffu, cm, 2));
                if (tig == 0) red[(wm * 32 + mf * 16 + hf * 8 + g) * 4 + wn] = cm;
            }
        __syncthreads();
#pragma unroll
        for (int mf = 0; mf < 2; mf++)
#pragma unroll
            for (int hf = 0; hf < 2; hf++) {
                const int row = wm * 32 + mf * 16 + hf * 8 + g;
                float mx = fmaxf(fmaxf(red[row * 4], red[row * 4 + 1]),
                                 fmaxf(red[row * 4 + 2], red[row * 4 + 3]));
                float mnew = fmaxf(mrun[mf][hf], mx);
                float f = __expf(mrun[mf][hf] - mnew);
                lrun[mf][hf] *= f;
#pragma unroll
                for (int nf = 0; nf < 4; nf++) {
                    oacc[mf][nf][hf * 2]     *= f;
                    oacc[mf][nf][hf * 2 + 1] *= f;
                }
                float rs = 0.0f;
#pragma unroll
                for (int nf = 0; nf < 2; nf++) {
                    float p0 = __expf(accs[mf][nf][hf * 2]     - mnew);
                    float p1 = __expf(accs[mf][nf][hf * 2 + 1] - mnew);
                    rs += p0 + p1;
                    const uint32_t cb = (uint32_t)(row * 144 + (wn * 16 + nf * 8 + tig * 2) * 2);
                    __half h0 = h_hi(p0), h1 = h_hi(p1);
                    *(uint32_t*)(smem + FQ_PH + cb) = pack_h2(h0, h1);
                    *(uint32_t*)(smem + FQ_PL + cb) = pack_h2(h_lo(p0, h0), h_lo(p1, h1));
                }
                rs += __shfl_xor_sync(0xffffffffu, rs, 1);
                rs += __shfl_xor_sync(0xffffffffu, rs, 2);
                lrun[mf][hf] += rs;
                mrun[mf][hf] = mnew;
            }
        __syncthreads();

        // ---- O += (Ph+Pl) @ Vh^T, fp16 x2 ----
#pragma unroll
        for (int kp = 0; kp < 4; kp++) {
            uint32_t ph[2][4], pl[2][4], vh[2][4];
#pragma unroll
            for (int mf = 0; mf < 2; mf++) {
                uint32_t off = (uint32_t)((wm * 32 + mf * 16 + (q4 & 1) * 8 + rq) * 144
                                          + kp * 32 + (q4 >> 1) * 16);
                ldsm_x4(ph[mf], sbase + FQ_PH + off);
                ldsm_x4(pl[mf], sbase + FQ_PL + off);
            }
#pragma unroll
            for (int pr = 0; pr < 2; pr++) {
                uint32_t off = (uint32_t)((wn * 32 + pr * 16 + (q4 >> 1) * 8 + rq) * 144
                                          + kp * 32 + (q4 & 1) * 16);
                ldsm_x4(vh[pr], sbase + FQ_PV + off);
            }
#pragma unroll
            for (int mf = 0; mf < 2; mf++)
#pragma unroll
                for (int nf = 0; nf < 4; nf++) {
                    const int pr = nf >> 1, w2 = (nf & 1) * 2;
                    mma16816(oacc[mf][nf], ph[mf], vh[pr][w2], vh[pr][w2 + 1]);
                    mma16816(oacc[mf][nf], pl[mf], vh[pr][w2], vh[pr][w2 + 1]);
                }
        }
        __syncthreads();                 // all reads of pk/pv done before overwrite
        if (c + 1 < 16) pf_chunk(c + 1);
    }

    // ---- epilogue ----
#pragma unroll
    for (int mf = 0; mf < 2; mf++)
#pragma unroll
        for (int hf = 0; hf < 2; hf++)
            if (tig == 0) red[(wm * 32 + mf * 16 + hf * 8 + g) * 4 + wn] = lrun[mf][hf];
    __syncthreads();
#pragma unroll
    for (int mf = 0; mf < 2; mf++)
#pragma unroll
        for (int hf = 0; hf < 2; hf++) {
            const int row = wm * 32 + mf * 16 + hf * 8 + g;
            float inv = 1.0f / (red[row * 4] + red[row * 4 + 1] + red[row * 4 + 2] + red[row * 4 + 3]);
            const long grow = (qrow0 + row) * 2048 + h * 128;
#pragma unroll
            for (int nf = 0; nf < 4; nf++) {
                const int col = wn * 32 + nf * 8 + tig * 2;
                float p0 = oacc[mf][nf][hf * 2] * inv, p1 = oacc[mf][nf][hf * 2 + 1] * inv;
                __half h0 = h_hi(p0), h1 = h_hi(p1);
                *(uint32_t*)&g_Ahi[grow + col] = pack_h2(h0, h1);
                *(uint32_t*)&g_Alo[grow + col] = pack_h2(h_lo(p0, h0), h_lo(p1, h1));
            }
        }
}

// ---------------- RoPE ----------------
__global__ __launch_bounds__(256) void rope_split(
    const float* __restrict__ cosp, const float* __restrict__ sinp)
{
    long idx = (long)blockIdx.x * blockDim.x + threadIdx.x;
    const long total = (long)BB * SS * (HH + KVH) * 64;
    if (idx >= total) return;
    int  d   = (int)(idx & 63);
    long t   = idx >> 6;
    int  hh  = (int)(t % (HH + KVH));
    long row = t / (HH + KVH);

    float c1 = cosp[row * 128 + d],  c2 = cosp[row * 128 + d + 64];
    float s1 = sinp[row * 128 + d],  s2 = sinp[row * 128 + d + 64];
    float* base = &g_qkv[row * 3072];

    if (hh < HH) {
        int col = hh * 128 + d;
        float x1 = base[col], x2 = base[col + 64];
        float r1 = (x1 * c1 - x2 * s1) * QK_SCALE;
        float r2 = (x2 * c2 + x1 * s2) * QK_SCALE;
        long o = row * 2048 + col;
        __half h1 = h_hi(r1), h2 = h_hi(r2);
        g_qhi[o] = h1;       g_qlo[o] = h_lo(r1, h1);
        g_qhi[o + 64] = h2;  g_qlo[o + 64] = h_lo(r2, h2);
    } else {
        int col = 2048 + (hh - HH) * 128 + d;
        float x1 = base[col], x2 = base[col + 64];
        base[col]      = x1 * c1 - x2 * s1;
        base[col + 64] = x2 * c2 + x1 * s2;
    }
}

// ---------------- host ----------------
extern "C" void kernel_launch(void* const* d_in, const int* in_sizes, int n_in,
                              void* d_out, int out_size)
{
    const float* hs   = (const float*)d_in[0];
    const float* cosp = (const float*)d_in[1];
    const float* sinp = (const float*)d_in[2];
    // d_in[3] attention_mask: constant over k -> softmax-invariant, unused
    const float* Wq   = (const float*)d_in[4];
    const float* bq   = (const float*)d_in[5];
    const float* Wk   = (const float*)d_in[6];
    const float* bk   = (const float*)d_in[7];
    const float* Wv   = (const float*)d_in[8];
    const float* bvp  = (const float*)d_in[9];
    const float* Wo   = (const float*)d_in[10];
    const float* E    = (const float*)d_in[11];
    const float* Fp   = (const float*)d_in[12];
    float* out = (float*)d_out;

    float *qkv, *bias, *pk;
    __half *Ahi, *Alo, *Wthi, *ETFhi, *ETFlo, *pkhi, *pklo;
    cudaGetSymbolAddress((void**)&qkv,   g_qkv);
    cudaGetSymbolAddress((void**)&bias,  g_bias);
    cudaGetSymbolAddress((void**)&pk,    g_pk);
    cudaGetSymbolAddress((void**)&Ahi,   g_Ahi);
    cudaGetSymbolAddress((void**)&Alo,   g_Alo);
    cudaGetSymbolAddress((void**)&Wthi,  g_Wthi);
    cudaGetSymbolAddress((void**)&ETFhi, g_ETFhi);
    cudaGetSymbolAddress((void**)&ETFlo, g_ETFlo);
    cudaGetSymbolAddress((void**)&pkhi,  g_pkhi);
    cudaGetSymbolAddress((void**)&pklo,  g_pklo);

    cudaFuncSetAttribute(gemm_mma,   cudaFuncAttributeMaxDynamicSharedMemorySize, GEMM_SMEM);
    cudaFuncSetAttribute(pkpv_mma,   cudaFuncAttributeMaxDynamicSharedMemorySize, GEMM_SMEM);
    cudaFuncSetAttribute(flash_attn, cudaFuncAttributeMaxDynamicSharedMemorySize, FL_SMEM);

    const dim3 blk(256);
    const int n4A = (int)((size_t)BB * SS * 2048 / 4);

    // prep (W lo planes skipped — unused by the x2 GEMM)
    split_h<<<(n4A + 255) / 256, blk>>>((const float4*)hs, (uint2*)Ahi, (uint2*)Alo, n4A);
    transpose_split<<<dim3(64, 64), blk>>>(Wq, Wthi, nullptr, 2048, 0,    2048);
    transpose_split<<<dim3(16, 64), blk>>>(Wk, Wthi, nullptr, 512,  2048, 2048);
    transpose_split<<<dim3(16, 64), blk>>>(Wv, Wthi, nullptr, 512,  2560, 2048);
    combine_bias<<<12, blk>>>(bq, bk, bvp, bias);

    // QKV (persistent, no tail wave): 64 m-tiles x 24 n-tiles = 1536
    gemm_mma<<<PERSIST_GRID, blk, GEMM_SMEM>>>(Ahi, Alo, Wthi, bias, qkv, 2048, 3072, 24, 1536);

    // Wo transpose immediately after QKV (stream order protects Wthi reuse);
    // off the flash->out critical path
    transpose_split<<<dim3(64, 64), blk>>>(Wo, Wthi, nullptr, 2048, 0, 2048);

    transpose_split<<<dim3(32, 128), blk>>>(E,  ETFhi, ETFlo, 1024, 0,    4096);
    transpose_split<<<dim3(32, 128), blk>>>(Fp, ETFhi, ETFlo, 1024, 1024, 4096);

    // RoPE
    {
        long total = (long)BB * SS * (HH + KVH) * 64;
        rope_split<<<(int)((total + 255) / 256), blk>>>(cosp, sinp);
    }

    // pk / pv
    kv_tsplit<<<dim3(128, 4, 16), blk>>>();
    pkpv_mma<<<dim3(1, 8, 16), blk, GEMM_SMEM>>>();
    {
        const int n4pk = 8 * KP * HDD / 4;
        split_h<<<(n4pk + 255) / 256, blk>>>((const float4*)pk, (uint2*)pkhi, (uint2*)pklo, n4pk);
    }
    pv_tsplit<<<dim3(32, 4, 8), blk>>>();

    // fused attention (BQ=64, occ 2)
    flash_attn<<<dim3(SS / 64, NBH), blk, FL_SMEM>>>();

    // out projection (persistent): 64 m-tiles x 16 n-tiles = 1024
    gemm_mma<<<PERSIST_GRID, blk, GEMM_SMEM>>>(Ahi, Alo, Wthi, nullptr, out, 2048, 2048, 16, 1024);
}

// round 16
// speedup vs baseline: 1.0400x; 1.0400x over previous
#include <cuda_runtime.h>
#include <cuda_fp16.h>
#include <cstdint>
#include <cstddef>

#define BB    2
#define SS    4096
#define HIDD  2048
#define HH    16
#define KVH   4
#define HDD   128
#define KP    1024
#define NBH   (BB * HH)
#define QK_SCALE 0.08838834764831843f

// ---------------- scratch ----------------
__device__ float g_qkv [(size_t)BB * SS * 3072];
__device__ float g_pv  [(size_t)8 * KP * HDD];
__device__ __half g_Ahi [(size_t)BB * SS * 2048];   // hs planes, then attn planes
__device__ __half g_Alo [(size_t)BB * SS * 2048];
__device__ __half g_Wthi[(size_t)3072 * 2048];
__device__ __half g_qhi [(size_t)BB * SS * 2048];
__device__ __half g_qlo [(size_t)BB * SS * 2048];
__device__ __half g_ETFhi[(size_t)2048 * 4096];
__device__ __half g_ETFlo[(size_t)2048 * 4096];
__device__ __half g_kvThi[(size_t)16 * 128 * 4096]; // hi only (B of pkpv)
__device__ __half g_pkhi[(size_t)8 * KP * HDD];
__device__ __half g_pklo[(size_t)8 * KP * HDD];     // scores stays 3-product
__device__ __half g_pvThi[(size_t)8 * HDD * KP];    // hi only (B of P@V)
__device__ float g_bias[3072];

// ---------------- PTX helpers ----------------
__device__ __forceinline__ uint32_t smem_u32(const void* p) {
    uint32_t a;
    asm("{ .reg .u64 t; cvta.to.shared.u64 t, %1; cvt.u32.u64 %0, t; }" : "=r"(a) : "l"(p));
    return a;
}
__device__ __forceinline__ void ldsm_x4(uint32_t* r, uint32_t addr) {
    asm volatile("ldmatrix.sync.aligned.m8n8.x4.shared.b16 {%0,%1,%2,%3}, [%4];"
                 : "=r"(r[0]), "=r"(r[1]), "=r"(r[2]), "=r"(r[3]) : "r"(addr));
}
__device__ __forceinline__ void mma16816(float* c, const uint32_t* a, uint32_t b0, uint32_t b1) {
    asm volatile("mma.sync.aligned.m16n8k16.row.col.f32.f16.f16.f32 "
                 "{%0,%1,%2,%3}, {%4,%5,%6,%7}, {%8,%9}, {%0,%1,%2,%3};"
                 : "+f"(c[0]), "+f"(c[1]), "+f"(c[2]), "+f"(c[3])
                 : "r"(a[0]), "r"(a[1]), "r"(a[2]), "r"(a[3]), "r"(b0), "r"(b1));
}
__device__ __forceinline__ void cp_async16(uint32_t dst, const void* src) {
    asm volatile("cp.async.cg.shared.global [%0], [%1], 16;" :: "r"(dst), "l"(src));
}
#define CP_COMMIT()  asm volatile("cp.async.commit_group;" ::: "memory")
#define CP_WAIT(n)   asm volatile("cp.async.wait_group %0;" :: "n"(n) : "memory")

__device__ __forceinline__ __half h_hi(float v) { return __float2half_rn(v); }
__device__ __forceinline__ __half h_lo(float v, __half h) {
    return __float2half_rn(v - __half2float(h));
}
__device__ __forceinline__ uint32_t pack_h2(__half a, __half b) {
    __half2 t(a, b);
    return *reinterpret_cast<uint32_t*>(&t);
}

// ---------------- splits / transposes ----------------
__global__ __launch_bounds__(256) void split_h(
    const float4* __restrict__ x, uint2* __restrict__ hi, uint2* __restrict__ lo, int n4)
{
    int i = blockIdx.x * 256 + threadIdx.x;
    if (i >= n4) return;
    float4 v = x[i];
    __half h0 = h_hi(v.x), h1 = h_hi(v.y), h2 = h_hi(v.z), h3 = h_hi(v.w);
    uint2 uh; uh.x = pack_h2(h0, h1); uh.y = pack_h2(h2, h3);
    uint2 ul; ul.x = pack_h2(h_lo(v.x, h0), h_lo(v.y, h1));
    ul.y = pack_h2(h_lo(v.z, h2), h_lo(v.w, h3));
    hi[i] = uh; lo[i] = ul;
}

// Tlo may be nullptr (lo plane unused -> skip the store)
__global__ __launch_bounds__(256) void transpose_split(
    const float* __restrict__ W, __half* __restrict__ Thi,
    __half* __restrict__ Tlo, int Nsrc, int rowOff, int ldT)
{
    __shared__ float t[32][33];
    const int n0 = blockIdx.x * 32, k0 = blockIdx.y * 32;
    const int tx = threadIdx.x & 31, ty = threadIdx.x >> 5;
#pragma unroll
    for (int j = 0; j < 32; j += 8)
        t[ty + j][tx] = W[(long)(k0 + ty + j) * Nsrc + n0 + tx];
    __syncthreads();
#pragma unroll
    for (int j = 0; j < 32; j += 8) {
        float v = t[tx][ty + j];
        long o = (long)(rowOff + n0 + ty + j) * ldT + k0 + tx;
        __half h = h_hi(v);
        Thi[o] = h;
        if (Tlo) Tlo[o] = h_lo(v, h);
    }
}

// k/v slices -> transposed hi plane only [z][128 d][4096 s]
__global__ __launch_bounds__(256) void kv_tsplit()
{
    __shared__ float t[32][33];
    const int z = blockIdx.z, sel = z >> 3, b = (z >> 2) & 1, kv = z & 3;
    const int s0 = blockIdx.x * 32, d0 = blockIdx.y * 32;
    const int tx = threadIdx.x & 31, ty = threadIdx.x >> 5;
    const float* src = g_qkv + (size_t)b * SS * 3072 + 2048 + sel * 512 + kv * 128;
#pragma unroll
    for (int j = 0; j < 32; j += 8)
        t[ty + j][tx] = src[(long)(s0 + ty + j) * 3072 + d0 + tx];
    __syncthreads();
    __half* dh = g_kvThi + (size_t)z * 128 * 4096;
#pragma unroll
    for (int j = 0; j < 32; j += 8)
        dh[(long)(d0 + ty + j) * 4096 + s0 + tx] = h_hi(t[tx][ty + j]);
}

// g_pv -> pvT hi plane only [sl][128 d][1024 key]
__global__ __launch_bounds__(256) void pv_tsplit()
{
    __shared__ float t[32][33];
    const int z = blockIdx.z;
    const int k0 = blockIdx.x * 32, d0 = blockIdx.y * 32;
    const int tx = threadIdx.x & 31, ty = threadIdx.x >> 5;
    const float* src = g_pv + (size_t)z * KP * HDD;
#pragma unroll
    for (int j = 0; j < 32; j += 8)
        t[ty + j][tx] = src[(long)(k0 + ty + j) * 128 + d0 + tx];
    __syncthreads();
    __half* dh = g_pvThi + (size_t)z * HDD * KP;
#pragma unroll
    for (int j = 0; j < 32; j += 8)
        dh[(long)(d0 + ty + j) * 1024 + k0 + tx] = h_hi(t[tx][ty + j]);
}

__global__ void combine_bias(const float* __restrict__ bq, const float* __restrict__ bk,
                             const float* __restrict__ bv, float* __restrict__ out)
{
    int i = blockIdx.x * 256 + threadIdx.x;
    if (i < 2048) out[i] = bq[i];
    else if (i < 2560) out[i] = bk[i - 2048];
    else if (i < 3072) out[i] = bv[i - 2560];
}

// ---------------- fp16 2-product GEMM, BK=64, 2 stages, 2 CTAs/SM ----------------
// smem tile: 128 rows x 128B data, 144B stride (ldsm conflict-free)
#define TILE_B  18432            // 128 * 144
#define STAGE_B (3 * TILE_B)     // Ah, Al, Bh = 55296
#define NSTAGE  2
#define GEMM_SMEM (NSTAGE * STAGE_B)   // 110592 -> 2 CTAs/SM

// EPI 0: fp32 C (+bias). EPI 1: fp16 hi/lo planes Chi/Clo (same rn-split as split_h).
template <int EPI>
__device__ __forceinline__ void mma_body(
    const __half* __restrict__ Ahi, const __half* __restrict__ Alo, long lda,
    const __half* __restrict__ Bhi, long ldb,
    const float* __restrict__ bias, float* __restrict__ C,
    __half* __restrict__ Chi, __half* __restrict__ Clo, long ldc,
    int K, long m0, long n0, char* smem)
{
    const uint32_t sbase = smem_u32(smem);
    const int tid  = threadIdx.x;
    const int lane = tid & 31;
    const int wid  = tid >> 5;
    const int wm   = wid >> 2;
    const int wn   = wid & 3;

    const __half* gsrc[3] = { Ahi, Alo, Bhi };

    // one stage = 3 tiles of 128 rows x 64 halves (128B); 12 cp.async/thread
    auto prefetch = [&](int kt, int st) {
#pragma unroll
        for (int i = 0; i < 12; i++) {
            const int t   = i >> 2;                 // tile 0..2
            const int idx = tid + (i & 3) * 256;    // 0..1023 within tile
            const int r   = idx >> 3;
            const int sg  = idx & 7;
            const long row = (t < 2 ? m0 : n0) + r;
            const long ld  = (t < 2 ? lda : ldb);
            cp_async16(sbase + st * STAGE_B + t * TILE_B + r * 144 + sg * 16,
                       gsrc[t] + row * ld + kt + sg * 8);
        }
        CP_COMMIT();
    };

    float acc[4][4][4];
#pragma unroll
    for (int i = 0; i < 4; i++)
#pragma unroll
        for (int j = 0; j < 4; j++)
#pragma unroll
            for (int k = 0; k < 4; k++) acc[i][j][k] = 0.0f;

    const int nch = K >> 6;
    prefetch(0, 0);

    const int q  = lane >> 3;
    const int rq = lane & 7;

    for (int ch = 0; ch < nch; ch++) {
        if (ch + 1 < nch) { prefetch((ch + 1) << 6, (ch + 1) & 1); CP_WAIT(1); }
        else              { CP_WAIT(0); }
        __syncthreads();

        const uint32_t sb = sbase + (ch & 1) * STAGE_B;
        const uint32_t AH = sb, AL = sb + TILE_B, BH = sb + 2 * TILE_B;

#pragma unroll
        for (int kc = 0; kc < 4; kc++) {
            const int koff = kc * 32;
            uint32_t ah[4][4], al[4][4], bh[2][4];
#pragma unroll
            for (int mf = 0; mf < 4; mf++) {
                uint32_t off = (uint32_t)((wm * 64 + mf * 16 + (q & 1) * 8 + rq) * 144
                                          + koff + (q >> 1) * 16);
                ldsm_x4(ah[mf], AH + off);
                ldsm_x4(al[mf], AL + off);
            }
#pragma unroll
            for (int pr = 0; pr < 2; pr++) {
                uint32_t off = (uint32_t)((wn * 32 + pr * 16 + (q >> 1) * 8 + rq) * 144
                                          + koff + (q & 1) * 16);
                ldsm_x4(bh[pr], BH + off);
            }
#pragma unroll
            for (int mf = 0; mf < 4; mf++)
#pragma unroll
                for (int nf = 0; nf < 4; nf++) {
                    const int pr = nf >> 1, w2 = (nf & 1) * 2;
                    mma16816(acc[mf][nf], ah[mf], bh[pr][w2], bh[pr][w2 + 1]);
                    mma16816(acc[mf][nf], al[mf], bh[pr][w2], bh[pr][w2 + 1]);
                }
        }
        __syncthreads();   // protect stage (ch&1) from iteration ch+1's prefetch of ch+2
    }

    const int g   = lane >> 2;
    const int tig = lane & 3;
#pragma unroll
    for (int mf = 0; mf < 4; mf++) {
        const long mrow = m0 + wm * 64 + mf * 16 + g;
#pragma unroll
        for (int nf = 0; nf < 4; nf++) {
            const long col = n0 + wn * 32 + nf * 8 + tig * 2;
            if (EPI == 0) {
                float b0 = 0.f, b1 = 0.f;
                if (bias) { b0 = bias[col]; b1 = bias[col + 1]; }
                float2 v0 = { acc[mf][nf][0] + b0, acc[mf][nf][1] + b1 };
                float2 v1 = { acc[mf][nf][2] + b0, acc[mf][nf][3] + b1 };
                *(float2*)&C[mrow * ldc + col]       = v0;
                *(float2*)&C[(mrow + 8) * ldc + col] = v1;
            } else {
                float p0 = acc[mf][nf][0], p1 = acc[mf][nf][1];
                float p2 = acc[mf][nf][2], p3 = acc[mf][nf][3];
                __half h0 = h_hi(p0), h1 = h_hi(p1), h2 = h_hi(p2), h3 = h_hi(p3);
                *(uint32_t*)&Chi[mrow * ldc + col]       = pack_h2(h0, h1);
                *(uint32_t*)&Chi[(mrow + 8) * ldc + col] = pack_h2(h2, h3);
                *(uint32_t*)&Clo[mrow * ldc + col]       = pack_h2(h_lo(p0, h0), h_lo(p1, h1));
                *(uint32_t*)&Clo[(mrow + 8) * ldc + col] = pack_h2(h_lo(p2, h2), h_lo(p3, h3));
            }
        }
    }
}

__global__ __launch_bounds__(256, 2) void gemm_mma(
    const __half* __restrict__ Ahi, const __half* __restrict__ Alo,
    const __half* __restrict__ Bhi,
    const float* __restrict__ bias, float* __restrict__ C, int K, int ldc)
{
    extern __shared__ char smem[];
    mma_body<0>(Ahi, Alo, K, Bhi, K, bias, C, nullptr, nullptr, ldc, K,
                (long)blockIdx.y * 128, (long)blockIdx.x * 128, smem);
}

// z 0..7: pk -> fp16 hi/lo planes directly (fused split). z 8..15: pv -> fp32.
__global__ __launch_bounds__(256, 2) void pkpv_mma()
{
    extern __shared__ char smem[];
    const int z = blockIdx.z, sel = z >> 3, sl = z & 7;
    const __half* Ah = g_ETFhi + (size_t)sel * 1024 * 4096;
    const __half* Al = g_ETFlo + (size_t)sel * 1024 * 4096;
    const __half* Bh = g_kvThi + (size_t)z * 128 * 4096;
    if (sel == 0) {
        __half* Chi = g_pkhi + (size_t)sl * KP * HDD;
        __half* Clo = g_pklo + (size_t)sl * KP * HDD;
        mma_body<1>(Ah, Al, 4096, Bh, 4096, nullptr, nullptr, Chi, Clo, 128, 4096,
                    (long)blockIdx.y * 128, 0, smem);
    } else {
        float* C = g_pv + (size_t)sl * KP * HDD;
        mma_body<0>(Ah, Al, 4096, Bh, 4096, nullptr, C, nullptr, nullptr, 128, 4096,
                    (long)blockIdx.y * 128, 0, smem);
    }
}

// ---------------- fused flash attention (fp16, BQ=128, occ 1) — R13 version ----------------
#define FQ_QH  0u
#define FQ_QL  34816u
#define FQ_PK(st) (69632u + (st) * 34816u)      // hi +0, lo +17408 (64 x 272)
#define FQ_PV(st) (139264u + (st) * 18432u)     // hi only (128 x 144)
#define FQ_PH  176128u                           // 128 x 144
#define FQ_PL  194560u
#define FQ_RED 212992u                           // 128 rows x 4 floats
#define FL_SMEM 215040

__global__ __launch_bounds__(256, 1) void flash_attn()
{
    extern __shared__ char smem[];
    const uint32_t sbase = smem_u32(smem);
    float* red = (float*)(smem + FQ_RED);

    const int tid  = threadIdx.x;
    const int lane = tid & 31;
    const int w    = tid >> 5;
    const int wm   = w >> 2;
    const int wn   = w & 3;
    const int q4   = lane >> 3;
    const int rq   = lane & 7;
    const int g    = lane >> 2;
    const int tig  = lane & 3;

    const int bh = blockIdx.y, b = bh >> 4, h = bh & 15;
    const int sl = b * KVH + (h >> 2);
    const long qrow0 = (long)b * SS + blockIdx.x * 128;
    const size_t pkOff = (size_t)sl * KP * HDD;
    const size_t pvOff = (size_t)sl * HDD * KP;

    auto pf_chunk = [&](int c, int st) {
#pragma unroll
        for (int i = 0; i < 8; i++) {              // pk hi+lo: 64 x 256B x2
            int idx = tid + i * 256;
            int plane = idx >> 10, rem = idx & 1023;
            int r = rem >> 4, sg = rem & 15;
            const __half* src = (plane ? g_pklo : g_pkhi) + pkOff + (size_t)(c * 64 + r) * 128 + sg * 8;
            cp_async16(sbase + FQ_PK(st) + plane * 17408u + r * 272 + sg * 16, src);
        }
#pragma unroll
        for (int i = 0; i < 4; i++) {              // pvT hi: 128 x 128B
            int idx = tid + i * 256;
            int r = idx >> 3, sg = idx & 7;
            const __half* src = g_pvThi + pvOff + (size_t)r * KP + c * 64 + sg * 8;
            cp_async16(sbase + FQ_PV(st) + r * 144 + sg * 16, src);
        }
        CP_COMMIT();
    };

    {   // q planes (128 rows x 16 seg x 2 planes) + chunk 0 as group 0
#pragma unroll
        for (int i = 0; i < 16; i++) {
            int idx = tid + i * 256;
            int plane = idx >> 11, rem = idx & 2047;
            int r = rem >> 4, sg = rem & 15;
            const __half* src = (plane ? g_qlo : g_qhi) + (qrow0 + r) * 2048 + h * 128 + sg * 8;
            cp_async16(sbase + (plane ? FQ_QL : FQ_QH) + r * 272 + sg * 16, src);
        }
        pf_chunk(0, 0);
    }
    pf_chunk(1, 1);

    float oacc[4][4][4];
#pragma unroll
    for (int i = 0; i < 4; i++)
#pragma unroll
        for (int j = 0; j < 4; j++)
#pragma unroll
            for (int k = 0; k < 4; k++) oacc[i][j][k] = 0.0f;
    float mrun[4][2], lrun[4][2];
#pragma unroll
    for (int i = 0; i < 4; i++)
#pragma unroll
        for (int j = 0; j < 2; j++) { mrun[i][j] = -1e30f; lrun[i][j] = 0.f; }

    for (int c = 0; c < 16; c++) {
        if (c + 1 < 16) { CP_WAIT(1); } else { CP_WAIT(0); }
        __syncthreads();
        const int st = c & 1;
        const uint32_t KH = sbase + FQ_PK(st), KL = KH + 17408u;
        const uint32_t VH = sbase + FQ_PV(st);

        // ---- S = q @ pk^T (128x64), fp16 x3 ----
        float accs[4][2][4];
#pragma unroll
        for (int i = 0; i < 4; i++)
#pragma unroll
            for (int j = 0; j < 2; j++)
#pragma unroll
                for (int k = 0; k < 4; k++) accs[i][j][k] = 0.0f;
#pragma unroll
        for (int ks = 0; ks < 8; ks++) {
            uint32_t qh[4][4], ql[4][4], kb[4], kl[4];
#pragma unroll
            for (int mf = 0; mf < 4; mf++) {
                uint32_t off = (uint32_t)((wm * 64 + mf * 16 + (q4 & 1) * 8 + rq) * 272
                                          + ks * 32 + (q4 >> 1) * 16);
                ldsm_x4(qh[mf], sbase + FQ_QH + off);
                ldsm_x4(ql[mf], sbase + FQ_QL + off);
            }
            {
                uint32_t off = (uint32_t)((wn * 16 + (q4 >> 1) * 8 + rq) * 272
                                          + ks * 32 + (q4 & 1) * 16);
                ldsm_x4(kb, KH + off);
                ldsm_x4(kl, KL + off);
            }
#pragma unroll
            for (int mf = 0; mf < 4; mf++)
#pragma unroll
                for (int nf = 0; nf < 2; nf++) {
                    const int w2 = nf * 2;
                    mma16816(accs[mf][nf], qh[mf], kb[w2], kb[w2 + 1]);
                    mma16816(accs[mf][nf], ql[mf], kb[w2], kb[w2 + 1]);
                    mma16816(accs[mf][nf], qh[mf], kl[w2], kl[w2 + 1]);
                }
        }

        // ---- online softmax ----
#pragma unroll
        for (int mf = 0; mf < 4; mf++)
#pragma unroll
            for (int hf = 0; hf < 2; hf++) {
                float cm = fmaxf(fmaxf(accs[mf][0][hf * 2], accs[mf][0][hf * 2 + 1]),
                                 fmaxf(accs[mf][1][hf * 2], accs[mf][1][hf * 2 + 1]));
                cm = fmaxf(cm, __shfl_xor_sync(0xffffffffu, cm, 1));
                cm = fmaxf(cm, __shfl_xor_sync(0xffffffffu, cm, 2));
                if (tig == 0) red[(wm * 64 + mf * 16 + hf * 8 + g) * 4 + wn] = cm;
            }
        __syncthreads();
#pragma unroll
        for (int mf = 0; mf < 4; mf++)
#pragma unroll
            for (int hf = 0; hf < 2; hf++) {
                const int row = wm * 64 + mf * 16 + hf * 8 + g;
                float mx = fmaxf(fmaxf(red[row * 4], red[row * 4 + 1]),
                                 fmaxf(red[row * 4 + 2], red[row * 4 + 3]));
                float mnew = fmaxf(mrun[mf][hf], mx);
                float f = __expf(mrun[mf][hf] - mnew);
                lrun[mf][hf] *= f;
#pragma unroll
                for (int nf = 0; nf < 4; nf++) {
                    oacc[mf][nf][hf * 2]     *= f;
                    oacc[mf][nf][hf * 2 + 1] *= f;
                }
                float rs = 0.0f;
#pragma unroll
                for (int nf = 0; nf < 2; nf++) {
                    float p0 = __expf(accs[mf][nf][hf * 2]     - mnew);
                    float p1 = __expf(accs[mf][nf][hf * 2 + 1] - mnew);
                    rs += p0 + p1;
                    const uint32_t cb = (uint32_t)(row * 144 + (wn * 16 + nf * 8 + tig * 2) * 2);
                    __half h0 = h_hi(p0), h1 = h_hi(p1);
                    *(uint32_t*)(smem + FQ_PH + cb) = pack_h2(h0, h1);
                    *(uint32_t*)(smem + FQ_PL + cb) = pack_h2(h_lo(p0, h0), h_lo(p1, h1));
                }
                rs += __shfl_xor_sync(0xffffffffu, rs, 1);
                rs += __shfl_xor_sync(0xffffffffu, rs, 2);
                lrun[mf][hf] += rs;
                mrun[mf][hf] = mnew;
            }
        __syncthreads();

        // ---- O += (Ph+Pl) @ Vh^T, fp16 x2 ----
#pragma unroll
        for (int kp = 0; kp < 4; kp++) {
            uint32_t ph[4][4], pl[4][4], vh[2][4];
#pragma unroll
            for (int mf = 0; mf < 4; mf++) {
                uint32_t off = (uint32_t)((wm * 64 + mf * 16 + (q4 & 1) * 8 + rq) * 144
                                          + kp * 32 + (q4 >> 1) * 16);
                ldsm_x4(ph[mf], sbase + FQ_PH + off);
                ldsm_x4(pl[mf], sbase + FQ_PL + off);
            }
#pragma unroll
            for (int pr = 0; pr < 2; pr++) {
                uint32_t off = (uint32_t)((wn * 32 + pr * 16 + (q4 >> 1) * 8 + rq) * 144
                                          + kp * 32 + (q4 & 1) * 16);
                ldsm_x4(vh[pr], VH + off);
            }
#pragma unroll
            for (int mf = 0; mf < 4; mf++)
#pragma unroll
                for (int nf = 0; nf < 4; nf++) {
                    const int pr = nf >> 1, w2 = (nf & 1) * 2;
                    mma16816(oacc[mf][nf], ph[mf], vh[pr][w2], vh[pr][w2 + 1]);
                    mma16816(oacc[mf][nf], pl[mf], vh[pr][w2], vh[pr][w2 + 1]);
                }
        }
        __syncthreads();
        if (c + 2 < 16) pf_chunk(c + 2, st);
    }

    // ---- epilogue ----
#pragma unroll
    for (int mf = 0; mf < 4; mf++)
#pragma unroll
        for (int hf = 0; hf < 2; hf++)
            if (tig == 0) red[(wm * 64 + mf * 16 + hf * 8 + g) * 4 + wn] = lrun[mf][hf];
    __syncthreads();
#pragma unroll
    for (int mf = 0; mf < 4; mf++)
#pragma unroll
        for (int hf = 0; hf < 2; hf++) {
            const int row = wm * 64 + mf * 16 + hf * 8 + g;
            float inv = 1.0f / (red[row * 4] + red[row * 4 + 1] + red[row * 4 + 2] + red[row * 4 + 3]);
            const long grow = (qrow0 + row) * 2048 + h * 128;
#pragma unroll
            for (int nf = 0; nf < 4; nf++) {
                const int col = wn * 32 + nf * 8 + tig * 2;
                float p0 = oacc[mf][nf][hf * 2] * inv, p1 = oacc[mf][nf][hf * 2 + 1] * inv;
                __half h0 = h_hi(p0), h1 = h_hi(p1);
                *(uint32_t*)&g_Ahi[grow + col] = pack_h2(h0, h1);
                *(uint32_t*)&g_Alo[grow + col] = pack_h2(h_lo(p0, h0), h_lo(p1, h1));
            }
        }
}

// ---------------- RoPE ----------------
__global__ __launch_bounds__(256) void rope_split(
    const float* __restrict__ cosp, const float* __restrict__ sinp)
{
    long idx = (long)blockIdx.x * blockDim.x + threadIdx.x;
    const long total = (long)BB * SS * (HH + KVH) * 64;
    if (idx >= total) return;
    int  d   = (int)(idx & 63);
    long t   = idx >> 6;
    int  hh  = (int)(t % (HH + KVH));
    long row = t / (HH + KVH);

    float c1 = cosp[row * 128 + d],  c2 = cosp[row * 128 + d + 64];
    float s1 = sinp[row * 128 + d],  s2 = sinp[row * 128 + d + 64];
    float* base = &g_qkv[row * 3072];

    if (hh < HH) {
        int col = hh * 128 + d;
        float x1 = base[col], x2 = base[col + 64];
        float r1 = (x1 * c1 - x2 * s1) * QK_SCALE;
        float r2 = (x2 * c2 + x1 * s2) * QK_SCALE;
        long o = row * 2048 + col;
        __half h1 = h_hi(r1), h2 = h_hi(r2);
        g_qhi[o] = h1;       g_qlo[o] = h_lo(r1, h1);
        g_qhi[o + 64] = h2;  g_qlo[o + 64] = h_lo(r2, h2);
    } else {
        int col = 2048 + (hh - HH) * 128 + d;
        float x1 = base[col], x2 = base[col + 64];
        base[col]      = x1 * c1 - x2 * s1;
        base[col + 64] = x2 * c2 + x1 * s2;
    }
}

// ---------------- host ----------------
extern "C" void kernel_launch(void* const* d_in, const int* in_sizes, int n_in,
                              void* d_out, int out_size)
{
    const float* hs   = (const float*)d_in[0];
    const float* cosp = (const float*)d_in[1];
    const float* sinp = (const float*)d_in[2];
    // d_in[3] attention_mask: constant over k -> softmax-invariant, unused
    const float* Wq   = (const float*)d_in[4];
    const float* bq   = (const float*)d_in[5];
    const float* Wk   = (const float*)d_in[6];
    const float* bk   = (const float*)d_in[7];
    const float* Wv   = (const float*)d_in[8];
    const float* bvp  = (const float*)d_in[9];
    const float* Wo   = (const float*)d_in[10];
    const float* E    = (const float*)d_in[11];
    const float* Fp   = (const float*)d_in[12];
    float* out = (float*)d_out;

    float *qkv, *bias;
    __half *Ahi, *Alo, *Wthi, *ETFhi, *ETFlo;
    cudaGetSymbolAddress((void**)&qkv,   g_qkv);
    cudaGetSymbolAddress((void**)&bias,  g_bias);
    cudaGetSymbolAddress((void**)&Ahi,   g_Ahi);
    cudaGetSymbolAddress((void**)&Alo,   g_Alo);
    cudaGetSymbolAddress((void**)&Wthi,  g_Wthi);
    cudaGetSymbolAddress((void**)&ETFhi, g_ETFhi);
    cudaGetSymbolAddress((void**)&ETFlo, g_ETFlo);

    cudaFuncSetAttribute(gemm_mma,   cudaFuncAttributeMaxDynamicSharedMemorySize, GEMM_SMEM);
    cudaFuncSetAttribute(pkpv_mma,   cudaFuncAttributeMaxDynamicSharedMemorySize, GEMM_SMEM);
    cudaFuncSetAttribute(flash_attn, cudaFuncAttributeMaxDynamicSharedMemorySize, FL_SMEM);

    const dim3 blk(256);
    const int n4A = (int)((size_t)BB * SS * 2048 / 4);

    // prep (W lo planes skipped — unused by the x2 GEMM)
    split_h<<<(n4A + 255) / 256, blk>>>((const float4*)hs, (uint2*)Ahi, (uint2*)Alo, n4A);
    transpose_split<<<dim3(64, 64), blk>>>(Wq, Wthi, nullptr, 2048, 0,    2048);
    transpose_split<<<dim3(16, 64), blk>>>(Wk, Wthi, nullptr, 512,  2048, 2048);
    transpose_split<<<dim3(16, 64), blk>>>(Wv, Wthi, nullptr, 512,  2560, 2048);
    combine_bias<<<12, blk>>>(bq, bk, bvp, bias);

    // QKV (fp16 x2, BK=64, occ 2)
    gemm_mma<<<dim3(24, 64), blk, GEMM_SMEM>>>(Ahi, Alo, Wthi, bias, qkv, 2048, 3072);

    transpose_split<<<dim3(32, 128), blk>>>(E,  ETFhi, ETFlo, 1024, 0,    4096);
    transpose_split<<<dim3(32, 128), blk>>>(Fp, ETFhi, ETFlo, 1024, 1024, 4096);

    // RoPE
    {
        long total = (long)BB * SS * (HH + KVH) * 64;
        rope_split<<<(int)((total + 255) / 256), blk>>>(cosp, sinp);
    }

    // pk / pv (pk planes written directly by the fused epilogue)
    kv_tsplit<<<dim3(128, 4, 16), blk>>>();
    pkpv_mma<<<dim3(1, 8, 16), blk, GEMM_SMEM>>>();
    pv_tsplit<<<dim3(32, 4, 8), blk>>>();

    // fused attention (BQ=128, occ 1)
    flash_attn<<<dim3(SS / 128, NBH), blk, FL_SMEM>>>();

    // out projection (fp16 x2, BK=64, occ 2)
    transpose_split<<<dim3(64, 64), blk>>>(Wo, Wthi, nullptr, 2048, 0, 2048);
    gemm_mma<<<dim3(16, 64), blk, GEMM_SMEM>>>(Ahi, Alo, Wthi, nullptr, out, 2048, 2048);
}

// round 17
// speedup vs baseline: 1.0514x; 1.0109x over previous
#include <cuda_runtime.h>
#include <cuda_fp16.h>
#include <cstdint>
#include <cstddef>

#define BB    2
#define SS    4096
#define HIDD  2048
#define HH    16
#define KVH   4
#define HDD   128
#define KP    1024
#define NBH   (BB * HH)
#define QK_SCALE 0.08838834764831843f

// ---------------- scratch ----------------
__device__ float g_qkv [(size_t)BB * SS * 3072];    // k/v region only used now
__device__ float g_pv  [(size_t)8 * KP * HDD];
__device__ __half g_Ahi [(size_t)BB * SS * 2048];   // hs planes, then attn planes
__device__ __half g_Alo [(size_t)BB * SS * 2048];
__device__ __half g_Wthi[(size_t)3072 * 2048];
__device__ __half g_qhi [(size_t)BB * SS * 2048];
__device__ __half g_qlo [(size_t)BB * SS * 2048];
__device__ __half g_ETFhi[(size_t)2048 * 4096];
__device__ __half g_ETFlo[(size_t)2048 * 4096];
__device__ __half g_kvThi[(size_t)16 * 128 * 4096]; // hi only (B of pkpv)
__device__ __half g_pkhi[(size_t)8 * KP * HDD];
__device__ __half g_pklo[(size_t)8 * KP * HDD];     // scores stays 3-product
__device__ __half g_pvThi[(size_t)8 * HDD * KP];    // hi only (B of P@V)
__device__ float g_bias[3072];

// ---------------- PTX helpers ----------------
__device__ __forceinline__ uint32_t smem_u32(const void* p) {
    uint32_t a;
    asm("{ .reg .u64 t; cvta.to.shared.u64 t, %1; cvt.u32.u64 %0, t; }" : "=r"(a) : "l"(p));
    return a;
}
__device__ __forceinline__ void ldsm_x4(uint32_t* r, uint32_t addr) {
    asm volatile("ldmatrix.sync.aligned.m8n8.x4.shared.b16 {%0,%1,%2,%3}, [%4];"
                 : "=r"(r[0]), "=r"(r[1]), "=r"(r[2]), "=r"(r[3]) : "r"(addr));
}
__device__ __forceinline__ void mma16816(float* c, const uint32_t* a, uint32_t b0, uint32_t b1) {
    asm volatile("mma.sync.aligned.m16n8k16.row.col.f32.f16.f16.f32 "
                 "{%0,%1,%2,%3}, {%4,%5,%6,%7}, {%8,%9}, {%0,%1,%2,%3};"
                 : "+f"(c[0]), "+f"(c[1]), "+f"(c[2]), "+f"(c[3])
                 : "r"(a[0]), "r"(a[1]), "r"(a[2]), "r"(a[3]), "r"(b0), "r"(b1));
}
__device__ __forceinline__ void cp_async16(uint32_t dst, const void* src) {
    asm volatile("cp.async.cg.shared.global [%0], [%1], 16;" :: "r"(dst), "l"(src));
}
#define CP_COMMIT()  asm volatile("cp.async.commit_group;" ::: "memory")
#define CP_WAIT(n)   asm volatile("cp.async.wait_group %0;" :: "n"(n) : "memory")

__device__ __forceinline__ __half h_hi(float v) { return __float2half_rn(v); }
__device__ __forceinline__ __half h_lo(float v, __half h) {
    return __float2half_rn(v - __half2float(h));
}
__device__ __forceinline__ uint32_t pack_h2(__half a, __half b) {
    __half2 t(a, b);
    return *reinterpret_cast<uint32_t*>(&t);
}

// ---------------- splits / transposes ----------------
__global__ __launch_bounds__(256) void split_h(
    const float4* __restrict__ x, uint2* __restrict__ hi, uint2* __restrict__ lo, int n4)
{
    int i = blockIdx.x * 256 + threadIdx.x;
    if (i >= n4) return;
    float4 v = x[i];
    __half h0 = h_hi(v.x), h1 = h_hi(v.y), h2 = h_hi(v.z), h3 = h_hi(v.w);
    uint2 uh; uh.x = pack_h2(h0, h1); uh.y = pack_h2(h2, h3);
    uint2 ul; ul.x = pack_h2(h_lo(v.x, h0), h_lo(v.y, h1));
    ul.y = pack_h2(h_lo(v.z, h2), h_lo(v.w, h3));
    hi[i] = uh; lo[i] = ul;
}

// Tlo may be nullptr (lo plane unused -> skip the store)
__global__ __launch_bounds__(256) void transpose_split(
    const float* __restrict__ W, __half* __restrict__ Thi,
    __half* __restrict__ Tlo, int Nsrc, int rowOff, int ldT)
{
    __shared__ float t[32][33];
    const int n0 = blockIdx.x * 32, k0 = blockIdx.y * 32;
    const int tx = threadIdx.x & 31, ty = threadIdx.x >> 5;
#pragma unroll
    for (int j = 0; j < 32; j += 8)
        t[ty + j][tx] = W[(long)(k0 + ty + j) * Nsrc + n0 + tx];
    __syncthreads();
#pragma unroll
    for (int j = 0; j < 32; j += 8) {
        float v = t[tx][ty + j];
        long o = (long)(rowOff + n0 + ty + j) * ldT + k0 + tx;
        __half h = h_hi(v);
        Thi[o] = h;
        if (Tlo) Tlo[o] = h_lo(v, h);
    }
}

// k/v slices -> transposed hi plane only [z][128 d][4096 s]
__global__ __launch_bounds__(256) void kv_tsplit()
{
    __shared__ float t[32][33];
    const int z = blockIdx.z, sel = z >> 3, b = (z >> 2) & 1, kv = z & 3;
    const int s0 = blockIdx.x * 32, d0 = blockIdx.y * 32;
    const int tx = threadIdx.x & 31, ty = threadIdx.x >> 5;
    const float* src = g_qkv + (size_t)b * SS * 3072 + 2048 + sel * 512 + kv * 128;
#pragma unroll
    for (int j = 0; j < 32; j += 8)
        t[ty + j][tx] = src[(long)(s0 + ty + j) * 3072 + d0 + tx];
    __syncthreads();
    __half* dh = g_kvThi + (size_t)z * 128 * 4096;
#pragma unroll
    for (int j = 0; j < 32; j += 8)
        dh[(long)(d0 + ty + j) * 4096 + s0 + tx] = h_hi(t[tx][ty + j]);
}

// g_pv -> pvT hi plane only [sl][128 d][1024 key]
__global__ __launch_bounds__(256) void pv_tsplit()
{
    __shared__ float t[32][33];
    const int z = blockIdx.z;
    const int k0 = blockIdx.x * 32, d0 = blockIdx.y * 32;
    const int tx = threadIdx.x & 31, ty = threadIdx.x >> 5;
    const float* src = g_pv + (size_t)z * KP * HDD;
#pragma unroll
    for (int j = 0; j < 32; j += 8)
        t[ty + j][tx] = src[(long)(k0 + ty + j) * 128 + d0 + tx];
    __syncthreads();
    __half* dh = g_pvThi + (size_t)z * HDD * KP;
#pragma unroll
    for (int j = 0; j < 32; j += 8)
        dh[(long)(d0 + ty + j) * 1024 + k0 + tx] = h_hi(t[tx][ty + j]);
}

__global__ void combine_bias(const float* __restrict__ bq, const float* __restrict__ bk,
                             const float* __restrict__ bv, float* __restrict__ out)
{
    int i = blockIdx.x * 256 + threadIdx.x;
    if (i < 2048) out[i] = bq[i];
    else if (i < 2560) out[i] = bk[i - 2048];
    else if (i < 3072) out[i] = bv[i - 2560];
}

// ---------------- fp16 2-product GEMM, BK=64, 2 stages, 2 CTAs/SM ----------------
// smem tile: 128 rows x 128B data, 144B stride (ldsm conflict-free)
#define TILE_B  18432            // 128 * 144
#define STAGE_B (3 * TILE_B)     // Ah, Al, Bh = 55296
#define NSTAGE  2
#define GEMM_SMEM (NSTAGE * STAGE_B)   // 110592 -> 2 CTAs/SM

// EPI 0: fp32 C (+bias). EPI 1: fp16 hi/lo planes Chi/Clo.
// EPI 3: QKV q-tile — stage acc+bias in smem fp32, RoPE+scale, fp16 split -> g_qhi/g_qlo.
template <int EPI>
__device__ __forceinline__ void mma_body(
    const __half* __restrict__ Ahi, const __half* __restrict__ Alo, long lda,
    const __half* __restrict__ Bhi, long ldb,
    const float* __restrict__ bias, float* __restrict__ C,
    __half* __restrict__ Chi, __half* __restrict__ Clo, long ldc,
    const float* __restrict__ cosp, const float* __restrict__ sinp,
    int K, long m0, long n0, char* smem)
{
    const uint32_t sbase = smem_u32(smem);
    const int tid  = threadIdx.x;
    const int lane = tid & 31;
    const int wid  = tid >> 5;
    const int wm   = wid >> 2;
    const int wn   = wid & 3;

    const __half* gsrc[3] = { Ahi, Alo, Bhi };

    auto prefetch = [&](int kt, int st) {
#pragma unroll
        for (int i = 0; i < 12; i++) {
            const int t   = i >> 2;
            const int idx = tid + (i & 3) * 256;
            const int r   = idx >> 3;
            const int sg  = idx & 7;
            const long row = (t < 2 ? m0 : n0) + r;
            const long ld  = (t < 2 ? lda : ldb);
            cp_async16(sbase + st * STAGE_B + t * TILE_B + r * 144 + sg * 16,
                       gsrc[t] + row * ld + kt + sg * 8);
        }
        CP_COMMIT();
    };

    float acc[4][4][4];
#pragma unroll
    for (int i = 0; i < 4; i++)
#pragma unroll
        for (int j = 0; j < 4; j++)
#pragma unroll
            for (int k = 0; k < 4; k++) acc[i][j][k] = 0.0f;

    const int nch = K >> 6;
    prefetch(0, 0);

    const int q  = lane >> 3;
    const int rq = lane & 7;

    for (int ch = 0; ch < nch; ch++) {
        if (ch + 1 < nch) { prefetch((ch + 1) << 6, (ch + 1) & 1); CP_WAIT(1); }
        else              { CP_WAIT(0); }
        __syncthreads();

        const uint32_t sb = sbase + (ch & 1) * STAGE_B;
        const uint32_t AH = sb, AL = sb + TILE_B, BH = sb + 2 * TILE_B;

#pragma unroll
        for (int kc = 0; kc < 4; kc++) {
            const int koff = kc * 32;
            uint32_t ah[4][4], al[4][4], bh[2][4];
#pragma unroll
            for (int mf = 0; mf < 4; mf++) {
                uint32_t off = (uint32_t)((wm * 64 + mf * 16 + (q & 1) * 8 + rq) * 144
                                          + koff + (q >> 1) * 16);
                ldsm_x4(ah[mf], AH + off);
                ldsm_x4(al[mf], AL + off);
            }
#pragma unroll
            for (int pr = 0; pr < 2; pr++) {
                uint32_t off = (uint32_t)((wn * 32 + pr * 16 + (q >> 1) * 8 + rq) * 144
                                          + koff + (q & 1) * 16);
                ldsm_x4(bh[pr], BH + off);
            }
#pragma unroll
            for (int mf = 0; mf < 4; mf++)
#pragma unroll
                for (int nf = 0; nf < 4; nf++) {
                    const int pr = nf >> 1, w2 = (nf & 1) * 2;
                    mma16816(acc[mf][nf], ah[mf], bh[pr][w2], bh[pr][w2 + 1]);
                    mma16816(acc[mf][nf], al[mf], bh[pr][w2], bh[pr][w2 + 1]);
                }
        }
        __syncthreads();   // protect stage (ch&1) from next prefetch; also frees smem for EPI=3
    }

    const int g   = lane >> 2;
    const int tig = lane & 3;

    if (EPI == 3) {
        // ---- stage acc + bias into smem fp32 (exact round-trip) ----
        float* Cs = (float*)smem;   // [128][132]
#pragma unroll
        for (int mf = 0; mf < 4; mf++) {
            const int lr = wm * 64 + mf * 16 + g;
#pragma unroll
            for (int nf = 0; nf < 4; nf++) {
                const int lc = wn * 32 + nf * 8 + tig * 2;
                float b0 = bias[n0 + lc], b1 = bias[n0 + lc + 1];
                Cs[lr * 132 + lc]           = acc[mf][nf][0] + b0;
                Cs[lr * 132 + lc + 1]       = acc[mf][nf][1] + b1;
                Cs[(lr + 8) * 132 + lc]     = acc[mf][nf][2] + b0;
                Cs[(lr + 8) * 132 + lc + 1] = acc[mf][nf][3] + b1;
            }
        }
        __syncthreads();
        // ---- RoPE + scale + fp16 split, store q planes (identical math to rope_split) ----
#pragma unroll
        for (int it = 0; it < 16; it++) {
            int idx = tid + it * 256;        // 0..4095 : 128 rows x 32 dp-pairs
            int r  = idx >> 5;
            int dp = (idx & 31) * 2;
            long row = m0 + r;               // = b*S + s
            const float* cb = cosp + row * 128;
            const float* sbp = sinp + row * 128;
            float c1a = cb[dp],      c1b = cb[dp + 1];
            float c2a = cb[dp + 64], c2b = cb[dp + 65];
            float s1a = sbp[dp],      s1b = sbp[dp + 1];
            float s2a = sbp[dp + 64], s2b = sbp[dp + 65];
            float x1a = Cs[r * 132 + dp],      x1b = Cs[r * 132 + dp + 1];
            float x2a = Cs[r * 132 + dp + 64], x2b = Cs[r * 132 + dp + 65];
            float r1a = (x1a * c1a - x2a * s1a) * QK_SCALE;
            float r1b = (x1b * c1b - x2b * s1b) * QK_SCALE;
            float r2a = (x2a * c2a + x1a * s2a) * QK_SCALE;
            float r2b = (x2b * c2b + x1b * s2b) * QK_SCALE;
            __half h1a = h_hi(r1a), h1b = h_hi(r1b), h2a = h_hi(r2a), h2b = h_hi(r2b);
            long o = row * 2048 + n0 + dp;
            *(uint32_t*)&g_qhi[o]      = pack_h2(h1a, h1b);
            *(uint32_t*)&g_qlo[o]      = pack_h2(h_lo(r1a, h1a), h_lo(r1b, h1b));
            *(uint32_t*)&g_qhi[o + 64] = pack_h2(h2a, h2b);
            *(uint32_t*)&g_qlo[o + 64] = pack_h2(h_lo(r2a, h2a), h_lo(r2b, h2b));
        }
        return;
    }

#pragma unroll
    for (int mf = 0; mf < 4; mf++) {
        const long mrow = m0 + wm * 64 + mf * 16 + g;
#pragma unroll
        for (int nf = 0; nf < 4; nf++) {
            const long col = n0 + wn * 32 + nf * 8 + tig * 2;
            if (EPI == 0) {
                float b0 = 0.f, b1 = 0.f;
                if (bias) { b0 = bias[col]; b1 = bias[col + 1]; }
                float2 v0 = { acc[mf][nf][0] + b0, acc[mf][nf][1] + b1 };
                float2 v1 = { acc[mf][nf][2] + b0, acc[mf][nf][3] + b1 };
                *(float2*)&C[mrow * ldc + col]       = v0;
                *(float2*)&C[(mrow + 8) * ldc + col] = v1;
            } else {
                float p0 = acc[mf][nf][0], p1 = acc[mf][nf][1];
                float p2 = acc[mf][nf][2], p3 = acc[mf][nf][3];
                __half h0 = h_hi(p0), h1 = h_hi(p1), h2 = h_hi(p2), h3 = h_hi(p3);
                *(uint32_t*)&Chi[mrow * ldc + col]       = pack_h2(h0, h1);
                *(uint32_t*)&Chi[(mrow + 8) * ldc + col] = pack_h2(h2, h3);
                *(uint32_t*)&Clo[mrow * ldc + col]       = pack_h2(h_lo(p0, h0), h_lo(p1, h1));
                *(uint32_t*)&Clo[(mrow + 8) * ldc + col] = pack_h2(h_lo(p2, h2), h_lo(p3, h3));
            }
        }
    }
}

__global__ __launch_bounds__(256, 2) void gemm_mma(
    const __half* __restrict__ Ahi, const __half* __restrict__ Alo,
    const __half* __restrict__ Bhi,
    const float* __restrict__ bias, float* __restrict__ C, int K, int ldc)
{
    extern __shared__ char smem[];
    mma_body<0>(Ahi, Alo, K, Bhi, K, bias, C, nullptr, nullptr, ldc,
                nullptr, nullptr, K,
                (long)blockIdx.y * 128, (long)blockIdx.x * 128, smem);
}

// QKV: n-tiles 0..15 are whole q heads -> fused RoPE epilogue; 16..23 (k/v) -> fp32
__global__ __launch_bounds__(256, 2) void qkv_mma(
    const __half* __restrict__ Ahi, const __half* __restrict__ Alo,
    const __half* __restrict__ Bhi, const float* __restrict__ bias,
    float* __restrict__ C,
    const float* __restrict__ cosp, const float* __restrict__ sinp)
{
    extern __shared__ char smem[];
    const long m0 = (long)blockIdx.y * 128;
    const long n0 = (long)blockIdx.x * 128;
    if (blockIdx.x < 16)
        mma_body<3>(Ahi, Alo, 2048, Bhi, 2048, bias, nullptr, nullptr, nullptr, 3072,
                    cosp, sinp, 2048, m0, n0, smem);
    else
        mma_body<0>(Ahi, Alo, 2048, Bhi, 2048, bias, C, nullptr, nullptr, 3072,
                    nullptr, nullptr, 2048, m0, n0, smem);
}

// z 0..7: pk -> fp16 hi/lo planes directly. z 8..15: pv -> fp32.
__global__ __launch_bounds__(256, 2) void pkpv_mma()
{
    extern __shared__ char smem[];
    const int z = blockIdx.z, sel = z >> 3, sl = z & 7;
    const __half* Ah = g_ETFhi + (size_t)sel * 1024 * 4096;
    const __half* Al = g_ETFlo + (size_t)sel * 1024 * 4096;
    const __half* Bh = g_kvThi + (size_t)z * 128 * 4096;
    if (sel == 0) {
        __half* Chi = g_pkhi + (size_t)sl * KP * HDD;
        __half* Clo = g_pklo + (size_t)sl * KP * HDD;
        mma_body<1>(Ah, Al, 4096, Bh, 4096, nullptr, nullptr, Chi, Clo, 128,
                    nullptr, nullptr, 4096, (long)blockIdx.y * 128, 0, smem);
    } else {
        float* C = g_pv + (size_t)sl * KP * HDD;
        mma_body<0>(Ah, Al, 4096, Bh, 4096, nullptr, C, nullptr, nullptr, 128,
                    nullptr, nullptr, 4096, (long)blockIdx.y * 128, 0, smem);
    }
}

// ---------------- fused flash attention (fp16, BQ=128, occ 1) ----------------
#define FQ_QH  0u
#define FQ_QL  34816u
#define FQ_PK(st) (69632u + (st) * 34816u)
#define FQ_PV(st) (139264u + (st) * 18432u)
#define FQ_PH  176128u
#define FQ_PL  194560u
#define FQ_RED 212992u
#define FL_SMEM 215040

__global__ __launch_bounds__(256, 1) void flash_attn()
{
    extern __shared__ char smem[];
    const uint32_t sbase = smem_u32(smem);
    float* red = (float*)(smem + FQ_RED);

    const int tid  = threadIdx.x;
    const int lane = tid & 31;
    const int w    = tid >> 5;
    const int wm   = w >> 2;
    const int wn   = w & 3;
    const int q4   = lane >> 3;
    const int rq   = lane & 7;
    const int g    = lane >> 2;
    const int tig  = lane & 3;

    const int bh = blockIdx.y, b = bh >> 4, h = bh & 15;
    const int sl = b * KVH + (h >> 2);
    const long qrow0 = (long)b * SS + blockIdx.x * 128;
    const size_t pkOff = (size_t)sl * KP * HDD;
    const size_t pvOff = (size_t)sl * HDD * KP;

    auto pf_chunk = [&](int c, int st) {
#pragma unroll
        for (int i = 0; i < 8; i++) {
            int idx = tid + i * 256;
            int plane = idx >> 10, rem = idx & 1023;
            int r = rem >> 4, sg = rem & 15;
            const __half* src = (plane ? g_pklo : g_pkhi) + pkOff + (size_t)(c * 64 + r) * 128 + sg * 8;
            cp_async16(sbase + FQ_PK(st) + plane * 17408u + r * 272 + sg * 16, src);
        }
#pragma unroll
        for (int i = 0; i < 4; i++) {
            int idx = tid + i * 256;
            int r = idx >> 3, sg = idx & 7;
            const __half* src = g_pvThi + pvOff + (size_t)r * KP + c * 64 + sg * 8;
            cp_async16(sbase + FQ_PV(st) + r * 144 + sg * 16, src);
        }
        CP_COMMIT();
    };

    {
#pragma unroll
        for (int i = 0; i < 16; i++) {
            int idx = tid + i * 256;
            int plane = idx >> 11, rem = idx & 2047;
            int r = rem >> 4, sg = rem & 15;
            const __half* src = (plane ? g_qlo : g_qhi) + (qrow0 + r) * 2048 + h * 128 + sg * 8;
            cp_async16(sbase + (plane ? FQ_QL : FQ_QH) + r * 272 + sg * 16, src);
        }
        pf_chunk(0, 0);
    }
    pf_chunk(1, 1);

    float oacc[4][4][4];
#pragma unroll
    for (int i = 0; i < 4; i++)
#pragma unroll
        for (int j = 0; j < 4; j++)
#pragma unroll
            for (int k = 0; k < 4; k++) oacc[i][j][k] = 0.0f;
    float mrun[4][2], lrun[4][2];
#pragma unroll
    for (int i = 0; i < 4; i++)
#pragma unroll
        for (int j = 0; j < 2; j++) { mrun[i][j] = -1e30f; lrun[i][j] = 0.f; }

    for (int c = 0; c < 16; c++) {
        if (c + 1 < 16) { CP_WAIT(1); } else { CP_WAIT(0); }
        __syncthreads();
        const int st = c & 1;
        const uint32_t KH = sbase + FQ_PK(st), KL = KH + 17408u;
        const uint32_t VH = sbase + FQ_PV(st);

        float accs[4][2][4];
#pragma unroll
        for (int i = 0; i < 4; i++)
#pragma unroll
            for (int j = 0; j < 2; j++)
#pragma unroll
                for (int k = 0; k < 4; k++) accs[i][j][k] = 0.0f;
#pragma unroll
        for (int ks = 0; ks < 8; ks++) {
            uint32_t qh[4][4], ql[4][4], kb[4], kl[4];
#pragma unroll
            for (int mf = 0; mf < 4; mf++) {
                uint32_t off = (uint32_t)((wm * 64 + mf * 16 + (q4 & 1) * 8 + rq) * 272
                                          + ks * 32 + (q4 >> 1) * 16);
                ldsm_x4(qh[mf], sbase + FQ_QH + off);
                ldsm_x4(ql[mf], sbase + FQ_QL + off);
            }
            {
                uint32_t off = (uint32_t)((wn * 16 + (q4 >> 1) * 8 + rq) * 272
                                          + ks * 32 + (q4 & 1) * 16);
                ldsm_x4(kb, KH + off);
                ldsm_x4(kl, KL + off);
            }
#pragma unroll
            for (int mf = 0; mf < 4; mf++)
#pragma unroll
                for (int nf = 0; nf < 2; nf++) {
                    const int w2 = nf * 2;
                    mma16816(accs[mf][nf], qh[mf], kb[w2], kb[w2 + 1]);
                    mma16816(accs[mf][nf], ql[mf], kb[w2], kb[w2 + 1]);
                    mma16816(accs[mf][nf], qh[mf], kl[w2], kl[w2 + 1]);
                }
        }

#pragma unroll
        for (int mf = 0; mf < 4; mf++)
#pragma unroll
            for (int hf = 0; hf < 2; hf++) {
                float cm = fmaxf(fmaxf(accs[mf][0][hf * 2], accs[mf][0][hf * 2 + 1]),
                                 fmaxf(accs[mf][1][hf * 2], accs[mf][1][hf * 2 + 1]));
                cm = fmaxf(cm, __shfl_xor_sync(0xffffffffu, cm, 1));
                cm = fmaxf(cm, __shfl_xor_sync(0xffffffffu, cm, 2));
                if (tig == 0) red[(wm * 64 + mf * 16 + hf * 8 + g) * 4 + wn] = cm;
            }
        __syncthreads();
#pragma unroll
        for (int mf = 0; mf < 4; mf++)
#pragma unroll
            for (int hf = 0; hf < 2; hf++) {
                const int row = wm * 64 + mf * 16 + hf * 8 + g;
                float mx = fmaxf(fmaxf(red[row * 4], red[row * 4 + 1]),
                                 fmaxf(red[row * 4 + 2], red[row * 4 + 3]));
                float mnew = fmaxf(mrun[mf][hf], mx);
                float f = __expf(mrun[mf][hf] - mnew);
                lrun[mf][hf] *= f;
#pragma unroll
                for (int nf = 0; nf < 4; nf++) {
                    oacc[mf][nf][hf * 2]     *= f;
                    oacc[mf][nf][hf * 2 + 1] *= f;
                }
                float rs = 0.0f;
#pragma unroll
                for (int nf = 0; nf < 2; nf++) {
                    float p0 = __expf(accs[mf][nf][hf * 2]     - mnew);
                    float p1 = __expf(accs[mf][nf][hf * 2 + 1] - mnew);
                    rs += p0 + p1;
                    const uint32_t cb = (uint32_t)(row * 144 + (wn * 16 + nf * 8 + tig * 2) * 2);
                    __half h0 = h_hi(p0), h1 = h_hi(p1);
                    *(uint32_t*)(smem + FQ_PH + cb) = pack_h2(h0, h1);
                    *(uint32_t*)(smem + FQ_PL + cb) = pack_h2(h_lo(p0, h0), h_lo(p1, h1));
                }
                rs += __shfl_xor_sync(0xffffffffu, rs, 1);
                rs += __shfl_xor_sync(0xffffffffu, rs, 2);
                lrun[mf][hf] += rs;
                mrun[mf][hf] = mnew;
            }
        __syncthreads();

#pragma unroll
        for (int kp = 0; kp < 4; kp++) {
            uint32_t ph[4][4], pl[4][4], vh[2][4];
#pragma unroll
            for (int mf = 0; mf < 4; mf++) {
                uint32_t off = (uint32_t)((wm * 64 + mf * 16 + (q4 & 1) * 8 + rq) * 144
                                          + kp * 32 + (q4 >> 1) * 16);
                ldsm_x4(ph[mf], sbase + FQ_PH + off);
                ldsm_x4(pl[mf], sbase + FQ_PL + off);
            }
#pragma unroll
            for (int pr = 0; pr < 2; pr++) {
                uint32_t off = (uint32_t)((wn * 32 + pr * 16 + (q4 >> 1) * 8 + rq) * 144
                                          + kp * 32 + (q4 & 1) * 16);
                ldsm_x4(vh[pr], VH + off);
            }
#pragma unroll
            for (int mf = 0; mf < 4; mf++)
#pragma unroll
                for (int nf = 0; nf < 4; nf++) {
                    const int pr = nf >> 1, w2 = (nf & 1) * 2;
                    mma16816(oacc[mf][nf], ph[mf], vh[pr][w2], vh[pr][w2 + 1]);
                    mma16816(oacc[mf][nf], pl[mf], vh[pr][w2], vh[pr][w2 + 1]);
                }
        }
        __syncthreads();
        if (c + 2 < 16) pf_chunk(c + 2, st);
    }

#pragma unroll
    for (int mf = 0; mf < 4; mf++)
#pragma unroll
        for (int hf = 0; hf < 2; hf++)
            if (tig == 0) red[(wm * 64 + mf * 16 + hf * 8 + g) * 4 + wn] = lrun[mf][hf];
    __syncthreads();
#pragma unroll
    for (int mf = 0; mf < 4; mf++)
#pragma unroll
        for (int hf = 0; hf < 2; hf++) {
            const int row = wm * 64 + mf * 16 + hf * 8 + g;
            float inv = 1.0f / (red[row * 4] + red[row * 4 + 1] + red[row * 4 + 2] + red[row * 4 + 3]);
            const long grow = (qrow0 + row) * 2048 + h * 128;
#pragma unroll
            for (int nf = 0; nf < 4; nf++) {
                const int col = wn * 32 + nf * 8 + tig * 2;
                float p0 = oacc[mf][nf][hf * 2] * inv, p1 = oacc[mf][nf][hf * 2 + 1] * inv;
                __half h0 = h_hi(p0), h1 = h_hi(p1);
                *(uint32_t*)&g_Ahi[grow + col] = pack_h2(h0, h1);
                *(uint32_t*)&g_Alo[grow + col] = pack_h2(h_lo(p0, h0), h_lo(p1, h1));
            }
        }
}

// ---------------- RoPE (k only — q is fused into the QKV epilogue) ----------------
__global__ __launch_bounds__(256) void rope_k(
    const float* __restrict__ cosp, const float* __restrict__ sinp)
{
    long idx = (long)blockIdx.x * blockDim.x + threadIdx.x;
    const long total = (long)BB * SS * KVH * 64;
    if (idx >= total) return;
    int  d   = (int)(idx & 63);
    long t   = idx >> 6;
    int  kvh = (int)(t % KVH);
    long row = t / KVH;

    float c1 = cosp[row * 128 + d],  c2 = cosp[row * 128 + d + 64];
    float s1 = sinp[row * 128 + d],  s2 = sinp[row * 128 + d + 64];
    float* base = &g_qkv[row * 3072];
    int col = 2048 + kvh * 128 + d;
    float x1 = base[col], x2 = base[col + 64];
    base[col]      = x1 * c1 - x2 * s1;
    base[col + 64] = x2 * c2 + x1 * s2;
}

// ---------------- host ----------------
extern "C" void kernel_launch(void* const* d_in, const int* in_sizes, int n_in,
                              void* d_out, int out_size)
{
    const float* hs   = (const float*)d_in[0];
    const float* cosp = (const float*)d_in[1];
    const float* sinp = (const float*)d_in[2];
    // d_in[3] attention_mask: constant over k -> softmax-invariant, unused
    const float* Wq   = (const float*)d_in[4];
    const float* bq   = (const float*)d_in[5];
    const float* Wk   = (const float*)d_in[6];
    const float* bk   = (const float*)d_in[7];
    const float* Wv   = (const float*)d_in[8];
    const float* bvp  = (const float*)d_in[9];
    const float* Wo   = (const float*)d_in[10];
    const float* E    = (const float*)d_in[11];
    const float* Fp   = (const float*)d_in[12];
    float* out = (float*)d_out;

    float *qkv, *bias;
    __half *Ahi, *Alo, *Wthi, *ETFhi, *ETFlo;
    cudaGetSymbolAddress((void**)&qkv,   g_qkv);
    cudaGetSymbolAddress((void**)&bias,  g_bias);
    cudaGetSymbolAddress((void**)&Ahi,   g_Ahi);
    cudaGetSymbolAddress((void**)&Alo,   g_Alo);
    cudaGetSymbolAddress((void**)&Wthi,  g_Wthi);
    cudaGetSymbolAddress((void**)&ETFhi, g_ETFhi);
    cudaGetSymbolAddress((void**)&ETFlo, g_ETFlo);

    cudaFuncSetAttribute(gemm_mma,   cudaFuncAttributeMaxDynamicSharedMemorySize, GEMM_SMEM);
    cudaFuncSetAttribute(qkv_mma,    cudaFuncAttributeMaxDynamicSharedMemorySize, GEMM_SMEM);
    cudaFuncSetAttribute(pkpv_mma,   cudaFuncAttributeMaxDynamicSharedMemorySize, GEMM_SMEM);
    cudaFuncSetAttribute(flash_attn, cudaFuncAttributeMaxDynamicSharedMemorySize, FL_SMEM);

    const dim3 blk(256);
    const int n4A = (int)((size_t)BB * SS * 2048 / 4);

    // prep
    split_h<<<(n4A + 255) / 256, blk>>>((const float4*)hs, (uint2*)Ahi, (uint2*)Alo, n4A);
    transpose_split<<<dim3(64, 64), blk>>>(Wq, Wthi, nullptr, 2048, 0,    2048);
    transpose_split<<<dim3(16, 64), blk>>>(Wk, Wthi, nullptr, 512,  2048, 2048);
    transpose_split<<<dim3(16, 64), blk>>>(Wv, Wthi, nullptr, 512,  2560, 2048);
    combine_bias<<<12, blk>>>(bq, bk, bvp, bias);

    // QKV with fused q-RoPE epilogue (q -> planes directly; k/v -> fp32 g_qkv)
    qkv_mma<<<dim3(24, 64), blk, GEMM_SMEM>>>(Ahi, Alo, Wthi, bias, qkv, cosp, sinp);

    transpose_split<<<dim3(32, 128), blk>>>(E,  ETFhi, ETFlo, 1024, 0,    4096);
    transpose_split<<<dim3(32, 128), blk>>>(Fp, ETFhi, ETFlo, 1024, 1024, 4096);

    // RoPE on k only
    {
        long total = (long)BB * SS * KVH * 64;
        rope_k<<<(int)((total + 255) / 256), blk>>>(cosp, sinp);
    }

    // pk / pv
    kv_tsplit<<<dim3(128, 4, 16), blk>>>();
    pkpv_mma<<<dim3(1, 8, 16), blk, GEMM_SMEM>>>();
    pv_tsplit<<<dim3(32, 4, 8), blk>>>();

    // fused attention (BQ=128, occ 1)
    flash_attn<<<dim3(SS / 128, NBH), blk, FL_SMEM>>>();

    // out projection (fp16 x2, BK=64, occ 2)
    transpose_split<<<dim3(64, 64), blk>>>(Wo, Wthi, nullptr, 2048, 0, 2048);
    gemm_mma<<<dim3(16, 64), blk, GEMM_SMEM>>>(Ahi, Alo, Wthi, nullptr, out, 2048, 2048);
}